// round 16
// baseline (speedup 1.0000x reference)
#include <cuda_runtime.h>
#include <cuda_fp16.h>
#include <math.h>
#include <stdint.h>

#define NN 50000
#define EE 800000
#define DD 256
#define HH 256
#define LL 40

// ---------------- scratch (device globals; no allocation allowed) ----------------
__device__ uint2  g_h16[(size_t)NN * 64];   // 25.6 MB (GEMM outputs, half2-packed)
__device__ uint2  g_x16[(size_t)NN * 64];   // 25.6 MB (agg outputs)
__device__ __half g_h2[(size_t)NN * LL];    // 4 MB (final-layer logits, fp16, stride 40)
__device__ int   g_src[EE];
__device__ int   g_dst[EE];
__device__ int   g_col[EE];
__device__ int   g_counts[NN];
__device__ int   g_rowptr[NN + 1];
__device__ int   g_cursor[NN];
__device__ float g_dinv[NN];
__device__ float g_als[NN];
__device__ float g_ald[NN];
__device__ float g_als2[NN];
__device__ float g_ald2[NN];
__device__ float g_colsum[DD];
__device__ float g_colsumsq[DD];
__device__ float g_mean[DD];
__device__ float g_istd[DD];
__device__ int   g_flag;  // 1 = edge_index is int64, 0 = int32
__device__ uint4 g_Whi4[(256 * 256) / 8];   // fp16 [n][k] transposed weight plane

__device__ __forceinline__ float lrelu(float v) { return v > 0.f ? v : 0.2f * v; }
__device__ __forceinline__ uint32_t swz128(uint32_t o) { return o ^ ((o >> 3) & 0x70); }

__device__ __forceinline__ uint32_t smem_u32(const void* p) {
    uint32_t a;
    asm("{ .reg .u64 t; cvta.to.shared.u64 t, %1; cvt.u32.u64 %0, t; }" : "=r"(a) : "l"(p));
    return a;
}

#define LDSM_X4(r0, r1, r2, r3, addr)                                               \
    asm volatile("ldmatrix.sync.aligned.m8n8.x4.shared.b16 {%0,%1,%2,%3}, [%4];"    \
                 : "=r"(r0), "=r"(r1), "=r"(r2), "=r"(r3) : "r"(addr))

#define MMAF16(d, a, b)                                                             \
    asm volatile("mma.sync.aligned.m16n8k16.row.col.f32.f16.f16.f32 "               \
                 "{%0,%1,%2,%3}, {%4,%5,%6,%7}, {%8,%9}, {%0,%1,%2,%3};"            \
                 : "+f"((d)[0]), "+f"((d)[1]), "+f"((d)[2]), "+f"((d)[3])           \
                 : "r"((a)[0]), "r"((a)[1]), "r"((a)[2]), "r"((a)[3]),              \
                   "r"((b)[0]), "r"((b)[1]))

#define CP_ASYNC16(dst, src, sz)                                                    \
    asm volatile("cp.async.cg.shared.global [%0], [%1], 16, %2;"                    \
                 :: "r"(dst), "l"(src), "r"(sz))
#define CP_COMMIT()  asm volatile("cp.async.commit_group;" ::: "memory")
#define CP_WAIT1()   asm volatile("cp.async.wait_group 1;" ::: "memory")
#define CP_WAIT0()   asm volatile("cp.async.wait_group 0;" ::: "memory")

// ---------------- setup kernels ----------------
__global__ void zero_kernel() {
    int i = blockIdx.x * blockDim.x + threadIdx.x;
    if (i < NN) g_counts[i] = 0;
}

__global__ void zero_al_kernel() {
    int i = blockIdx.x * blockDim.x + threadIdx.x;
    if (i < NN) { g_als[i] = 0.f; g_ald[i] = 0.f; g_als2[i] = 0.f; g_ald2[i] = 0.f; }
}

__global__ void detect_kernel(const unsigned int* __restrict__ p) {
    if (blockIdx.x == 0 && threadIdx.x == 0) {
        int is64 = 1;
        for (int i = 0; i < 64; i++)
            if (p[2 * i + 1] != 0u) { is64 = 0; break; }
        g_flag = is64;
    }
}

__global__ void convert_kernel(const void* __restrict__ ei) {
    int e = blockIdx.x * blockDim.x + threadIdx.x;
    if (e >= EE) return;
    int s, d;
    if (g_flag) {
        const long long* p = (const long long*)ei;
        s = (int)p[e]; d = (int)p[EE + e];
    } else {
        const int* p = (const int*)ei;
        s = p[e]; d = p[EE + e];
    }
    g_src[e] = s;
    g_dst[e] = d;
    atomicAdd(&g_counts[d], 1);
}

__global__ void stats_kernel(const float* __restrict__ x) {
    __shared__ float4 ss[256], ss2[256];
    int cg = threadIdx.x & 63;
    int rl = threadIdx.x >> 6;
    int g4 = gridDim.x * 4;
    float4 s = make_float4(0.f, 0.f, 0.f, 0.f);
    float4 s2 = make_float4(0.f, 0.f, 0.f, 0.f);
    for (int r = blockIdx.x * 4 + rl; r < NN; r += g4 * 4) {
        float4 v[4];
#pragma unroll
        for (int j = 0; j < 4; j++) {
            int rr = r + j * g4;
            v[j] = (rr < NN) ? ((const float4*)x)[(size_t)rr * 64 + cg]
                             : make_float4(0.f, 0.f, 0.f, 0.f);
        }
#pragma unroll
        for (int j = 0; j < 4; j++) {
            s.x += v[j].x; s.y += v[j].y; s.z += v[j].z; s.w += v[j].w;
            s2.x += v[j].x * v[j].x; s2.y += v[j].y * v[j].y;
            s2.z += v[j].z * v[j].z; s2.w += v[j].w * v[j].w;
        }
    }
    ss[threadIdx.x] = s; ss2[threadIdx.x] = s2;
    __syncthreads();
    if (threadIdx.x < 64) {
#pragma unroll
        for (int k = 1; k < 4; k++) {
            float4 t = ss[threadIdx.x + 64 * k], t2 = ss2[threadIdx.x + 64 * k];
            s.x += t.x; s.y += t.y; s.z += t.z; s.w += t.w;
            s2.x += t2.x; s2.y += t2.y; s2.z += t2.z; s2.w += t2.w;
        }
        int c = threadIdx.x * 4;
        atomicAdd(&g_colsum[c + 0], s.x); atomicAdd(&g_colsum[c + 1], s.y);
        atomicAdd(&g_colsum[c + 2], s.z); atomicAdd(&g_colsum[c + 3], s.w);
        atomicAdd(&g_colsumsq[c + 0], s2.x); atomicAdd(&g_colsumsq[c + 1], s2.y);
        atomicAdd(&g_colsumsq[c + 2], s2.z); atomicAdd(&g_colsumsq[c + 3], s2.w);
    }
}

__global__ void finalize_kernel() {
    int c = threadIdx.x;
    float mean = g_colsum[c] / (float)NN;
    float var = (g_colsumsq[c] - (float)NN * mean * mean) / (float)(NN - 1);
    g_mean[c] = mean;
    g_istd[c] = rsqrtf(var);
}

__global__ void dinv_kernel() {
    int i = blockIdx.x * blockDim.x + threadIdx.x;
    if (i < NN) g_dinv[i] = rsqrtf((float)(g_counts[i] + 1));
}

__global__ void scan_kernel() {
    __shared__ int warpsum[32];
    __shared__ int s_off;
    int tid = threadIdx.x;
    int lane = tid & 31, wid = tid >> 5;
    if (tid == 0) s_off = 0;
    __syncthreads();
    for (int base = 0; base < NN; base += 1024) {
        int i = base + tid;
        int v = (i < NN) ? g_counts[i] : 0;
        int xs = v;
#pragma unroll
        for (int d = 1; d < 32; d <<= 1) {
            int t = __shfl_up_sync(0xffffffffu, xs, d);
            if (lane >= d) xs += t;
        }
        if (lane == 31) warpsum[wid] = xs;
        __syncthreads();
        if (wid == 0) {
            int w = warpsum[lane];
#pragma unroll
            for (int d = 1; d < 32; d <<= 1) {
                int t = __shfl_up_sync(0xffffffffu, w, d);
                if (lane >= d) w += t;
            }
            warpsum[lane] = w;
        }
        __syncthreads();
        int excl = xs - v + (wid ? warpsum[wid - 1] : 0);
        int off = s_off;
        if (i < NN) { g_rowptr[i] = off + excl; g_cursor[i] = off + excl; }
        __syncthreads();
        if (tid == 1023) s_off = off + excl + v;
        __syncthreads();
    }
    if (tid == 0) g_rowptr[NN] = s_off;
}

__global__ void fill_kernel() {
    int e = blockIdx.x * blockDim.x + threadIdx.x;
    if (e >= EE) return;
    int d = g_dst[e];
    int p = atomicAdd(&g_cursor[d], 1);
    g_col[p] = g_src[e];
}

// ---------------- weight transpose -> fp16 plane (zeroes stats accumulators) --------------
__global__ void splitW_kernel(const float* __restrict__ W) {
    int idx = blockIdx.x * blockDim.x + threadIdx.x;
    if (idx < 256) { g_colsum[idx] = 0.f; g_colsumsq[idx] = 0.f; }
    if (idx >= 256 * 256) return;
    int k = idx >> 8;
    int n = idx & 255;
    ((__half*)g_Whi4)[n * 256 + k] = __float2half_rn(W[idx]);
}

// W2 [256,40] -> plane rows 0..127 (rows 40..127 zero), [n][k] fp16
__global__ void splitW2_kernel(const float* __restrict__ W2) {
    int idx = blockIdx.x * blockDim.x + threadIdx.x;   // 128*256
    if (idx >= 128 * 256) return;
    int n = idx >> 8;
    int k = idx & 255;
    float v = (n < LL) ? W2[k * LL + n] : 0.f;
    ((__half*)g_Whi4)[n * 256 + k] = __float2half_rn(v);
}

// ---------------- mma.sync fp16 GEMM with cp.async double-buffered pipeline --------------
// doStd: stage A from fp32 x with inline standardization (GEMM-1); else cp.async fp16 A.
#define CB_A   0
#define CB_B   16384
#define CB_SZ  32768
#define MMA_SMEM (2 * CB_SZ)

__global__ void __launch_bounds__(256, 2) mma_gemm_kernel(
    const __half* __restrict__ A16, const float* __restrict__ A32,
    const __half* __restrict__ B_g,
    __half* __restrict__ C16, int M, int ostride, int ncols, int doStd,
    int doAl, float* __restrict__ alsP, float* __restrict__ aldP,
    const float* __restrict__ a_src, const float* __restrict__ a_dst) {
    extern __shared__ char smem[];
    uint32_t sb = smem_u32(smem);
    int tid = threadIdx.x;
    int wid = tid >> 5, lane = tid & 31;
    int bm = blockIdx.y * 128;
    int bn = blockIdx.x * 128;
    int wm = (wid >> 1) * 32;
    int wn = (wid & 1) * 64;

    float acc[2][8][4];
#pragma unroll
    for (int mt = 0; mt < 2; mt++)
#pragma unroll
        for (int nt = 0; nt < 8; nt++)
#pragma unroll
            for (int r = 0; r < 4; r++) acc[mt][nt][r] = 0.f;

    uint32_t b_row[4], b_cb;
#pragma unroll
    for (int ntp = 0; ntp < 4; ntp++)
        b_row[ntp] = (uint32_t)(wn + ntp * 16 + (lane & 7) + ((lane >> 4) << 3));
    b_cb = (uint32_t)(((lane >> 3) & 1) * 16);

#define STAGE(ch, buf)                                                                  \
    do {                                                                                \
        int _k0 = (ch) * 64;                                                            \
        uint32_t _base = sb + (buf) * CB_SZ;                                            \
        if (doStd) {                                                                    \
            _Pragma("unroll")                                                           \
            for (int _i = 0; _i < 8; _i++) {                                            \
                int _lin = tid + _i * 256;                                              \
                int _row = _lin >> 4;                                                   \
                int _c4 = (_lin & 15) * 4;                                              \
                int _gr = bm + _row;                                                    \
                float4 _v = make_float4(0.f, 0.f, 0.f, 0.f);                            \
                if (_gr < M) _v = *(const float4*)(A32 + (size_t)_gr * 256 + _k0 + _c4);\
                int _cc = _k0 + _c4;                                                    \
                _v.x = (_v.x - g_mean[_cc + 0]) * g_istd[_cc + 0];                      \
                _v.y = (_v.y - g_mean[_cc + 1]) * g_istd[_cc + 1];                      \
                _v.z = (_v.z - g_mean[_cc + 2]) * g_istd[_cc + 2];                      \
                _v.w = (_v.w - g_mean[_cc + 3]) * g_istd[_cc + 3];                      \
                __half2 _h01 = __floats2half2_rn(_v.x, _v.y);                           \
                __half2 _h23 = __floats2half2_rn(_v.z, _v.w);                           \
                uint32_t _so = swz128((uint32_t)(_row * 128 + _c4 * 2));                \
                *(uint2*)(smem + (buf) * CB_SZ + CB_A + _so) =                          \
                    make_uint2(*(uint32_t*)&_h01, *(uint32_t*)&_h23);                   \
            }                                                                           \
        } else {                                                                        \
            _Pragma("unroll")                                                           \
            for (int _i = 0; _i < 4; _i++) {                                            \
                int _lin = tid + _i * 256;                                              \
                int _row = _lin >> 3, _sg = _lin & 7;                                   \
                uint32_t _so = swz128((uint32_t)(_row * 128 + _sg * 16));               \
                int _gr = bm + _row;                                                    \
                const __half* _sa = A16 + (size_t)(_gr < M ? _gr : M - 1) * 256 + _k0 + _sg * 8; \
                CP_ASYNC16(_base + CB_A + _so, _sa, (_gr < M) ? 16 : 0);                \
            }                                                                           \
        }                                                                               \
        _Pragma("unroll")                                                               \
        for (int _i = 0; _i < 4; _i++) {                                                \
            int _lin = tid + _i * 256;                                                  \
            int _row = _lin >> 3, _sg = _lin & 7;                                       \
            uint32_t _so = swz128((uint32_t)(_row * 128 + _sg * 16));                   \
            const __half* _sb2 = B_g + (size_t)(bn + _row) * 256 + _k0 + _sg * 8;       \
            CP_ASYNC16(_base + CB_B + _so, _sb2, 16);                                   \
        }                                                                               \
        CP_COMMIT();                                                                    \
    } while (0)

    STAGE(0, 0);
    for (int ch = 0; ch < 4; ch++) {
        int buf = ch & 1;
        if (ch < 3) { STAGE(ch + 1, buf ^ 1); CP_WAIT1(); }
        else        { CP_WAIT0(); }
        __syncthreads();
        uint32_t base = sb + buf * CB_SZ;
#pragma unroll
        for (int ks = 0; ks < 4; ks++) {
            uint32_t kb = (uint32_t)(ks * 32);
            uint32_t a[2][4];
#pragma unroll
            for (int mt = 0; mt < 2; mt++) {
                uint32_t row = (uint32_t)(wm + mt * 16 + (lane & 15));
                uint32_t cb = (uint32_t)((lane >> 4) * 16) + kb;
                uint32_t ad = base + CB_A + swz128(row * 128 + cb);
                LDSM_X4(a[mt][0], a[mt][1], a[mt][2], a[mt][3], ad);
            }
            uint32_t bh[8][2];
#pragma unroll
            for (int ntp = 0; ntp < 4; ntp++) {
                uint32_t bo = swz128(b_row[ntp] * 128 + b_cb + kb);
                LDSM_X4(bh[2 * ntp][0], bh[2 * ntp][1], bh[2 * ntp + 1][0],
                        bh[2 * ntp + 1][1], base + CB_B + bo);
            }
#pragma unroll
            for (int mt = 0; mt < 2; mt++)
#pragma unroll
                for (int nt = 0; nt < 8; nt++)
                    MMAF16(acc[mt][nt], a[mt], bh[nt]);
        }
        __syncthreads();
    }
#undef STAGE

    // ---- epilogue: fp16 store (guarded by ncols) + optional fused attention logits ----
#pragma unroll
    for (int mt = 0; mt < 2; mt++) {
        int r0 = bm + wm + mt * 16 + (lane >> 2);
        int r1 = r0 + 8;
        float ds0 = 0.f, dd0 = 0.f, ds1 = 0.f, dd1 = 0.f;
#pragma unroll
        for (int nt = 0; nt < 8; nt++) {
            int col = bn + wn + nt * 8 + (lane & 3) * 2;
            if (col < ncols) {
                if (r0 < M) *(__half2*)(C16 + (size_t)r0 * ostride + col) =
                    __floats2half2_rn(acc[mt][nt][0], acc[mt][nt][1]);
                if (r1 < M) *(__half2*)(C16 + (size_t)r1 * ostride + col) =
                    __floats2half2_rn(acc[mt][nt][2], acc[mt][nt][3]);
            }
            if (doAl) {
                float as0 = a_src[col], as1 = a_src[col + 1];
                float ad0 = a_dst[col], ad1 = a_dst[col + 1];
                ds0 += acc[mt][nt][0] * as0 + acc[mt][nt][1] * as1;
                dd0 += acc[mt][nt][0] * ad0 + acc[mt][nt][1] * ad1;
                ds1 += acc[mt][nt][2] * as0 + acc[mt][nt][3] * as1;
                dd1 += acc[mt][nt][2] * ad0 + acc[mt][nt][3] * ad1;
            }
        }
        if (doAl) {
#pragma unroll
            for (int o = 1; o < 4; o <<= 1) {
                ds0 += __shfl_xor_sync(0xffffffffu, ds0, o);
                dd0 += __shfl_xor_sync(0xffffffffu, dd0, o);
                ds1 += __shfl_xor_sync(0xffffffffu, ds1, o);
                dd1 += __shfl_xor_sync(0xffffffffu, dd1, o);
            }
            if ((lane & 3) == 0) {
                if (r0 < M) { atomicAdd(&alsP[r0], ds0); atomicAdd(&aldP[r0], dd0); }
                if (r1 < M) { atomicAdd(&alsP[r1], ds1); atomicAdd(&aldP[r1], dd1); }
            }
        }
    }
}

// ---- fp16 row gather/store helpers ----
__device__ __forceinline__ void h16_accum(const uint2* __restrict__ hp, int idx, float w,
                                          float4& a0, float4& a1) {
    uint2 u0 = hp[idx];
    uint2 u1 = hp[idx + 32];
    float2 f0 = __half22float2(*(__half2*)&u0.x);
    float2 f1 = __half22float2(*(__half2*)&u0.y);
    float2 f2 = __half22float2(*(__half2*)&u1.x);
    float2 f3 = __half22float2(*(__half2*)&u1.y);
    a0.x += w * f0.x; a0.y += w * f0.y; a0.z += w * f1.x; a0.w += w * f1.y;
    a1.x += w * f2.x; a1.y += w * f2.y; a1.z += w * f3.x; a1.w += w * f3.y;
}

__device__ __forceinline__ void h16_store(uint2* __restrict__ o, int node, int lane,
                                          const float4& a0, const float4& a1) {
    __half2 h01 = __floats2half2_rn(a0.x, a0.y);
    __half2 h23 = __floats2half2_rn(a0.z, a0.w);
    uint2 u0 = make_uint2(*(uint32_t*)&h01, *(uint32_t*)&h23);
    __half2 h45 = __floats2half2_rn(a1.x, a1.y);
    __half2 h67 = __floats2half2_rn(a1.z, a1.w);
    uint2 u1 = make_uint2(*(uint32_t*)&h45, *(uint32_t*)&h67);
    o[(size_t)node * 64 + lane] = u0;
    o[(size_t)node * 64 + lane + 32] = u1;
}

// ---------------- GCN aggregate (warp per dst node, fp16 in/out, unroll-4) ---------------
__global__ void gcn_agg_kernel(const uint2* __restrict__ h, const float* __restrict__ bias,
                               uint2* __restrict__ out) {
    int t = blockIdx.x * blockDim.x + threadIdx.x;
    int node = t >> 5;
    int lane = t & 31;
    if (node >= NN) return;
    int beg = g_rowptr[node], end = g_rowptr[node + 1];
    float di = g_dinv[node];
    float4 a0 = make_float4(0.f, 0.f, 0.f, 0.f);
    float4 a1 = make_float4(0.f, 0.f, 0.f, 0.f);
    h16_accum(h, node * 64 + lane, di * di, a0, a1);
    int e = beg;
    for (; e + 4 <= end; e += 4) {
        int s0 = g_col[e], s1 = g_col[e + 1], s2 = g_col[e + 2], s3 = g_col[e + 3];
        float w0 = g_dinv[s0] * di, w1 = g_dinv[s1] * di;
        float w2 = g_dinv[s2] * di, w3 = g_dinv[s3] * di;
        h16_accum(h, s0 * 64 + lane, w0, a0, a1);
        h16_accum(h, s1 * 64 + lane, w1, a0, a1);
        h16_accum(h, s2 * 64 + lane, w2, a0, a1);
        h16_accum(h, s3 * 64 + lane, w3, a0, a1);
    }
    for (; e < end; e++) {
        int s = g_col[e];
        h16_accum(h, s * 64 + lane, g_dinv[s] * di, a0, a1);
    }
    float4 b0 = ((const float4*)bias)[lane];
    float4 b1 = ((const float4*)bias)[lane + 32];
    a0.x = fmaxf(a0.x + b0.x, 0.f); a0.y = fmaxf(a0.y + b0.y, 0.f);
    a0.z = fmaxf(a0.z + b0.z, 0.f); a0.w = fmaxf(a0.w + b0.w, 0.f);
    a1.x = fmaxf(a1.x + b1.x, 0.f); a1.y = fmaxf(a1.y + b1.y, 0.f);
    a1.z = fmaxf(a1.z + b1.z, 0.f); a1.w = fmaxf(a1.w + b1.w, 0.f);
    h16_store(out, node, lane, a0, a1);
}

// ---------------- GAT aggregate with segment softmax (fp16 in/out, unroll-4) -------------
__global__ void gat_agg_kernel(const uint2* __restrict__ h, const float* __restrict__ bias,
                               uint2* __restrict__ out,
                               const float* __restrict__ alsP, const float* __restrict__ aldP) {
    int t = blockIdx.x * blockDim.x + threadIdx.x;
    int node = t >> 5;
    int lane = t & 31;
    if (node >= NN) return;
    int beg = g_rowptr[node], end = g_rowptr[node + 1];
    float aldi = aldP[node];
    float e_self = lrelu(alsP[node] + aldi);
    float m = e_self;
    for (int e = beg + lane; e < end; e += 32)
        m = fmaxf(m, lrelu(alsP[g_col[e]] + aldi));
    for (int o = 16; o; o >>= 1) m = fmaxf(m, __shfl_xor_sync(0xffffffffu, m, o));
    float z = __expf(e_self - m);
    float4 a0 = make_float4(0.f, 0.f, 0.f, 0.f);
    float4 a1 = make_float4(0.f, 0.f, 0.f, 0.f);
    h16_accum(h, node * 64 + lane, z, a0, a1);
    int e = beg;
    for (; e + 4 <= end; e += 4) {
        int s0 = g_col[e], s1 = g_col[e + 1], s2 = g_col[e + 2], s3 = g_col[e + 3];
        float w0 = __expf(lrelu(alsP[s0] + aldi) - m);
        float w1 = __expf(lrelu(alsP[s1] + aldi) - m);
        float w2 = __expf(lrelu(alsP[s2] + aldi) - m);
        float w3 = __expf(lrelu(alsP[s3] + aldi) - m);
        z += w0 + w1 + w2 + w3;
        h16_accum(h, s0 * 64 + lane, w0, a0, a1);
        h16_accum(h, s1 * 64 + lane, w1, a0, a1);
        h16_accum(h, s2 * 64 + lane, w2, a0, a1);
        h16_accum(h, s3 * 64 + lane, w3, a0, a1);
    }
    for (; e < end; e++) {
        int s = g_col[e];
        float w = __expf(lrelu(alsP[s] + aldi) - m);
        z += w;
        h16_accum(h, s * 64 + lane, w, a0, a1);
    }
    float inv = 1.0f / z;
    float4 b0 = ((const float4*)bias)[lane];
    float4 b1 = ((const float4*)bias)[lane + 32];
    a0.x = fmaxf(a0.x * inv + b0.x, 0.f); a0.y = fmaxf(a0.y * inv + b0.y, 0.f);
    a0.z = fmaxf(a0.z * inv + b0.z, 0.f); a0.w = fmaxf(a0.w * inv + b0.w, 0.f);
    a1.x = fmaxf(a1.x * inv + b1.x, 0.f); a1.y = fmaxf(a1.y * inv + b1.y, 0.f);
    a1.z = fmaxf(a1.z * inv + b1.z, 0.f); a1.w = fmaxf(a1.w * inv + b1.w, 0.f);
    h16_store(out, node, lane, a0, a1);
}

// ---------------- final GCN (L=40) + log_softmax: 20 active lanes x half2 ----------------
__global__ void gcn2_kernel(const __half* __restrict__ h2, const float* __restrict__ b2,
                            float* __restrict__ out) {
    int t = blockIdx.x * blockDim.x + threadIdx.x;
    int node = t >> 5;
    int lane = t & 31;
    if (node >= NN) return;
    int beg = g_rowptr[node], end = g_rowptr[node + 1];
    float di = g_dinv[node];
    bool act = lane < 20;
    const __half2* hp = (const __half2*)h2;   // row stride 20 half2
    float2 acc = make_float2(0.f, 0.f);
    float w = di * di;
    if (act) {
        float2 f = __half22float2(hp[node * 20 + lane]);
        acc.x = w * f.x; acc.y = w * f.y;
    }
    int e = beg;
    for (; e + 4 <= end; e += 4) {
        int s0 = g_col[e], s1 = g_col[e + 1], s2 = g_col[e + 2], s3 = g_col[e + 3];
        float w0 = g_dinv[s0] * di, w1 = g_dinv[s1] * di;
        float w2 = g_dinv[s2] * di, w3 = g_dinv[s3] * di;
        if (act) {
            float2 f0 = __half22float2(hp[s0 * 20 + lane]);
            float2 f1 = __half22float2(hp[s1 * 20 + lane]);
            float2 f2 = __half22float2(hp[s2 * 20 + lane]);
            float2 f3 = __half22float2(hp[s3 * 20 + lane]);
            acc.x += w0 * f0.x + w1 * f1.x + w2 * f2.x + w3 * f3.x;
            acc.y += w0 * f0.y + w1 * f1.y + w2 * f2.y + w3 * f3.y;
        }
    }
    for (; e < end; e++) {
        int s = g_col[e];
        float we = g_dinv[s] * di;
        if (act) {
            float2 f = __half22float2(hp[s * 20 + lane]);
            acc.x += we * f.x; acc.y += we * f.y;
        }
    }
    float v0 = act ? acc.x + b2[lane * 2] : -INFINITY;
    float v1 = act ? acc.y + b2[lane * 2 + 1] : -INFINITY;
    float m = fmaxf(v0, v1);
    for (int o = 16; o; o >>= 1) m = fmaxf(m, __shfl_xor_sync(0xffffffffu, m, o));
    float z = act ? (expf(v0 - m) + expf(v1 - m)) : 0.f;
    for (int o = 16; o; o >>= 1) z += __shfl_xor_sync(0xffffffffu, z, o);
    float ls = logf(z);
    if (act)
        *(float2*)(out + (size_t)node * LL + lane * 2) = make_float2(v0 - m - ls, v1 - m - ls);
}

// ---------------- launch ----------------
extern "C" void kernel_launch(void* const* d_in, const int* in_sizes, int n_in,
                              void* d_out, int out_size) {
    const float* x   = (const float*)d_in[0];
    const void*  ei  = d_in[1];
    const float* W1  = (const float*)d_in[2];
    const float* b1  = (const float*)d_in[3];
    const float* Wg  = (const float*)d_in[4];
    const float* a_s = (const float*)d_in[5];
    const float* a_d = (const float*)d_in[6];
    const float* bg  = (const float*)d_in[7];
    const float* W2  = (const float*)d_in[8];
    const float* b2  = (const float*)d_in[9];
    float* out = (float*)d_out;

    uint2 *pH16, *pX16;
    __half* pH2;
    __half* pWhi;
    float *pAls, *pAld, *pAls2, *pAld2;
    cudaGetSymbolAddress((void**)&pH16, g_h16);
    cudaGetSymbolAddress((void**)&pX16, g_x16);
    cudaGetSymbolAddress((void**)&pH2, g_h2);
    cudaGetSymbolAddress((void**)&pWhi, g_Whi4);
    cudaGetSymbolAddress((void**)&pAls, g_als);
    cudaGetSymbolAddress((void**)&pAld, g_ald);
    cudaGetSymbolAddress((void**)&pAls2, g_als2);
    cudaGetSymbolAddress((void**)&pAld2, g_ald2);

    cudaFuncSetAttribute(mma_gemm_kernel, cudaFuncAttributeMaxDynamicSharedMemorySize, MMA_SMEM);

    const int tpb = 256;
    dim3 gMMA(2, (NN + 127) / 128);
    dim3 gMMA2(1, (NN + 127) / 128);
    int warpGrid = (NN * 32 + tpb - 1) / tpb;
    int zg = (NN + tpb - 1) / tpb;

    // side stream + fork/join events (capture-compatible fork/join pattern)
    cudaStream_t s2;
    cudaStreamCreateWithFlags(&s2, cudaStreamNonBlocking);
    cudaEvent_t evFork, evCsr, evG1, evW, evG3, evW2;
    cudaEventCreateWithFlags(&evFork, cudaEventDisableTiming);
    cudaEventCreateWithFlags(&evCsr, cudaEventDisableTiming);
    cudaEventCreateWithFlags(&evG1, cudaEventDisableTiming);
    cudaEventCreateWithFlags(&evW, cudaEventDisableTiming);
    cudaEventCreateWithFlags(&evG3, cudaEventDisableTiming);
    cudaEventCreateWithFlags(&evW2, cudaEventDisableTiming);

    // ---- fork: CSR build on s2, concurrent with stats/GEMM-1 on main ----
    cudaEventRecord(evFork, 0);
    cudaStreamWaitEvent(s2, evFork, 0);
    zero_kernel<<<zg, tpb, 0, s2>>>();
    detect_kernel<<<1, 32, 0, s2>>>((const unsigned int*)ei);
    convert_kernel<<<(EE + tpb - 1) / tpb, tpb, 0, s2>>>(ei);
    dinv_kernel<<<zg, tpb, 0, s2>>>();
    scan_kernel<<<1, 1024, 0, s2>>>();
    fill_kernel<<<(EE + tpb - 1) / tpb, tpb, 0, s2>>>();
    cudaEventRecord(evCsr, s2);

    // ---- main: GEMM-1 path (standardize fused into A-staging, reads x fp32 directly) ----
    splitW_kernel<<<(256 * 256) / tpb, tpb>>>(W1);   // also zeroes colsum/colsumsq
    stats_kernel<<<296, 256>>>(x);
    finalize_kernel<<<1, 256>>>();
    mma_gemm_kernel<<<gMMA, 256, MMA_SMEM>>>((const __half*)0, x, pWhi,
                                             (__half*)pH16, NN, 256, 256, 1, 0,
                                             pAls, pAld, a_s, a_d);
    cudaEventRecord(evG1, 0);

    // fork: splitW(Wg) + zero both al-buffer pairs on s2, overlapping gcn_agg on main
    cudaStreamWaitEvent(s2, evG1, 0);
    splitW_kernel<<<(256 * 256) / tpb, tpb, 0, s2>>>(Wg);
    zero_al_kernel<<<zg, tpb, 0, s2>>>();
    cudaEventRecord(evW, s2);

    // main: join CSR, then GCN aggregate (+ReLU) -> x16
    cudaStreamWaitEvent(0, evCsr, 0);
    gcn_agg_kernel<<<warpGrid, tpb>>>(pH16, b1, pX16);

    // GAT layer 1 (+ReLU): logits -> als/ald
    cudaStreamWaitEvent(0, evW, 0);
    mma_gemm_kernel<<<gMMA, 256, MMA_SMEM>>>((const __half*)pX16, (const float*)0, pWhi,
                                             (__half*)pH16, NN, 256, 256, 0, 1,
                                             pAls, pAld, a_s, a_d);
    gat_agg_kernel<<<warpGrid, tpb>>>(pH16, bg, pX16, pAls, pAld);

    // GAT layer 2 (+ReLU): logits -> als2/ald2 (pre-zeroed on s2)
    mma_gemm_kernel<<<gMMA, 256, MMA_SMEM>>>((const __half*)pX16, (const float*)0, pWhi,
                                             (__half*)pH16, NN, 256, 256, 0, 1,
                                             pAls2, pAld2, a_s, a_d);
    cudaEventRecord(evG3, 0);

    // fork: splitW2(W2) on s2 overlapping gat_agg2 on main
    cudaStreamWaitEvent(s2, evG3, 0);
    splitW2_kernel<<<(128 * 256) / tpb, tpb, 0, s2>>>(W2);
    cudaEventRecord(evW2, s2);

    gat_agg_kernel<<<warpGrid, tpb>>>(pH16, bg, pX16, pAls2, pAld2);

    // GCN layer 2 (tensor-core, N padded to 128, fp16 out, stride LL halves) + log_softmax
    cudaStreamWaitEvent(0, evW2, 0);
    mma_gemm_kernel<<<gMMA2, 256, MMA_SMEM>>>((const __half*)pX16, (const float*)0, pWhi,
                                              pH2, NN, LL, LL, 0, 0,
                                              pAls, pAld, a_s, a_d);
    gcn2_kernel<<<warpGrid, tpb>>>(pH2, b2, out);

    cudaEventDestroy(evFork);
    cudaEventDestroy(evCsr);
    cudaEventDestroy(evG1);
    cudaEventDestroy(evW);
    cudaEventDestroy(evG3);
    cudaEventDestroy(evW2);
    cudaStreamDestroy(s2);
}

// round 17
// speedup vs baseline: 1.0266x; 1.0266x over previous
#include <cuda_runtime.h>
#include <cuda_fp16.h>
#include <math.h>
#include <stdint.h>

#define NN 50000
#define EE 800000
#define DD 256
#define HH 256
#define LL 40

// ---------------- scratch (device globals; no allocation allowed) ----------------
__device__ uint2  g_h16[(size_t)NN * 64];   // 25.6 MB (GEMM outputs, half2-packed)
__device__ uint2  g_x16[(size_t)NN * 64];   // 25.6 MB (agg outputs)
__device__ __half g_h2[(size_t)NN * LL];    // 4 MB (final-layer logits, fp16, stride 40)
__device__ int   g_src[EE];
__device__ int   g_dst[EE];
__device__ int   g_col[EE];
__device__ int   g_counts[NN];
__device__ int   g_rowptr[NN + 1];
__device__ int   g_cursor[NN];
__device__ float g_dinv[NN];
__device__ float g_als[NN];
__device__ float g_ald[NN];
__device__ float g_als2[NN];
__device__ float g_ald2[NN];
__device__ float g_colsum[DD];
__device__ float g_colsumsq[DD];
__device__ float g_mean[DD];
__device__ float g_istd[DD];
__device__ int   g_flag;  // 1 = edge_index is int64, 0 = int32
__device__ uint4 g_Whi4[(256 * 256) / 8];   // fp16 [n][k] transposed weight plane

__device__ __forceinline__ float lrelu(float v) { return v > 0.f ? v : 0.2f * v; }
__device__ __forceinline__ uint32_t swz128(uint32_t o) { return o ^ ((o >> 3) & 0x70); }

__device__ __forceinline__ uint32_t smem_u32(const void* p) {
    uint32_t a;
    asm("{ .reg .u64 t; cvta.to.shared.u64 t, %1; cvt.u32.u64 %0, t; }" : "=r"(a) : "l"(p));
    return a;
}

#define LDSM_X4(r0, r1, r2, r3, addr)                                               \
    asm volatile("ldmatrix.sync.aligned.m8n8.x4.shared.b16 {%0,%1,%2,%3}, [%4];"    \
                 : "=r"(r0), "=r"(r1), "=r"(r2), "=r"(r3) : "r"(addr))

#define MMAF16(d, a, b)                                                             \
    asm volatile("mma.sync.aligned.m16n8k16.row.col.f32.f16.f16.f32 "               \
                 "{%0,%1,%2,%3}, {%4,%5,%6,%7}, {%8,%9}, {%0,%1,%2,%3};"            \
                 : "+f"((d)[0]), "+f"((d)[1]), "+f"((d)[2]), "+f"((d)[3])           \
                 : "r"((a)[0]), "r"((a)[1]), "r"((a)[2]), "r"((a)[3]),              \
                   "r"((b)[0]), "r"((b)[1]))

#define CP_ASYNC16(dst, src, sz)                                                    \
    asm volatile("cp.async.cg.shared.global [%0], [%1], 16, %2;"                    \
                 :: "r"(dst), "l"(src), "r"(sz))
#define CP_COMMIT()  asm volatile("cp.async.commit_group;" ::: "memory")
#define CP_WAIT1()   asm volatile("cp.async.wait_group 1;" ::: "memory")
#define CP_WAIT0()   asm volatile("cp.async.wait_group 0;" ::: "memory")

// ---------------- setup kernels ----------------
__global__ void zero_kernel() {
    int i = blockIdx.x * blockDim.x + threadIdx.x;
    if (i < NN) g_counts[i] = 0;
}

__global__ void zero_al_kernel() {
    int i = blockIdx.x * blockDim.x + threadIdx.x;
    if (i < NN) { g_als[i] = 0.f; g_ald[i] = 0.f; g_als2[i] = 0.f; g_ald2[i] = 0.f; }
}

__global__ void detect_kernel(const unsigned int* __restrict__ p) {
    if (blockIdx.x == 0 && threadIdx.x == 0) {
        int is64 = 1;
        for (int i = 0; i < 64; i++)
            if (p[2 * i + 1] != 0u) { is64 = 0; break; }
        g_flag = is64;
    }
}

__global__ void convert_kernel(const void* __restrict__ ei) {
    int e = blockIdx.x * blockDim.x + threadIdx.x;
    if (e >= EE) return;
    int s, d;
    if (g_flag) {
        const long long* p = (const long long*)ei;
        s = (int)p[e]; d = (int)p[EE + e];
    } else {
        const int* p = (const int*)ei;
        s = p[e]; d = p[EE + e];
    }
    g_src[e] = s;
    g_dst[e] = d;
    atomicAdd(&g_counts[d], 1);
}

__global__ void stats_kernel(const float* __restrict__ x) {
    __shared__ float4 ss[256], ss2[256];
    int cg = threadIdx.x & 63;
    int rl = threadIdx.x >> 6;
    int g4 = gridDim.x * 4;
    float4 s = make_float4(0.f, 0.f, 0.f, 0.f);
    float4 s2 = make_float4(0.f, 0.f, 0.f, 0.f);
    for (int r = blockIdx.x * 4 + rl; r < NN; r += g4 * 4) {
        float4 v[4];
#pragma unroll
        for (int j = 0; j < 4; j++) {
            int rr = r + j * g4;
            v[j] = (rr < NN) ? ((const float4*)x)[(size_t)rr * 64 + cg]
                             : make_float4(0.f, 0.f, 0.f, 0.f);
        }
#pragma unroll
        for (int j = 0; j < 4; j++) {
            s.x += v[j].x; s.y += v[j].y; s.z += v[j].z; s.w += v[j].w;
            s2.x += v[j].x * v[j].x; s2.y += v[j].y * v[j].y;
            s2.z += v[j].z * v[j].z; s2.w += v[j].w * v[j].w;
        }
    }
    ss[threadIdx.x] = s; ss2[threadIdx.x] = s2;
    __syncthreads();
    if (threadIdx.x < 64) {
#pragma unroll
        for (int k = 1; k < 4; k++) {
            float4 t = ss[threadIdx.x + 64 * k], t2 = ss2[threadIdx.x + 64 * k];
            s.x += t.x; s.y += t.y; s.z += t.z; s.w += t.w;
            s2.x += t2.x; s2.y += t2.y; s2.z += t2.z; s2.w += t2.w;
        }
        int c = threadIdx.x * 4;
        atomicAdd(&g_colsum[c + 0], s.x); atomicAdd(&g_colsum[c + 1], s.y);
        atomicAdd(&g_colsum[c + 2], s.z); atomicAdd(&g_colsum[c + 3], s.w);
        atomicAdd(&g_colsumsq[c + 0], s2.x); atomicAdd(&g_colsumsq[c + 1], s2.y);
        atomicAdd(&g_colsumsq[c + 2], s2.z); atomicAdd(&g_colsumsq[c + 3], s2.w);
    }
}

__global__ void finalize_kernel() {
    int c = threadIdx.x;
    float mean = g_colsum[c] / (float)NN;
    float var = (g_colsumsq[c] - (float)NN * mean * mean) / (float)(NN - 1);
    g_mean[c] = mean;
    g_istd[c] = rsqrtf(var);
}

__global__ void dinv_kernel() {
    int i = blockIdx.x * blockDim.x + threadIdx.x;
    if (i < NN) g_dinv[i] = rsqrtf((float)(g_counts[i] + 1));
}

__global__ void scan_kernel() {
    __shared__ int warpsum[32];
    __shared__ int s_off;
    int tid = threadIdx.x;
    int lane = tid & 31, wid = tid >> 5;
    if (tid == 0) s_off = 0;
    __syncthreads();
    for (int base = 0; base < NN; base += 1024) {
        int i = base + tid;
        int v = (i < NN) ? g_counts[i] : 0;
        int xs = v;
#pragma unroll
        for (int d = 1; d < 32; d <<= 1) {
            int t = __shfl_up_sync(0xffffffffu, xs, d);
            if (lane >= d) xs += t;
        }
        if (lane == 31) warpsum[wid] = xs;
        __syncthreads();
        if (wid == 0) {
            int w = warpsum[lane];
#pragma unroll
            for (int d = 1; d < 32; d <<= 1) {
                int t = __shfl_up_sync(0xffffffffu, w, d);
                if (lane >= d) w += t;
            }
            warpsum[lane] = w;
        }
        __syncthreads();
        int excl = xs - v + (wid ? warpsum[wid - 1] : 0);
        int off = s_off;
        if (i < NN) { g_rowptr[i] = off + excl; g_cursor[i] = off + excl; }
        __syncthreads();
        if (tid == 1023) s_off = off + excl + v;
        __syncthreads();
    }
    if (tid == 0) g_rowptr[NN] = s_off;
}

__global__ void fill_kernel() {
    int e = blockIdx.x * blockDim.x + threadIdx.x;
    if (e >= EE) return;
    int d = g_dst[e];
    int p = atomicAdd(&g_cursor[d], 1);
    g_col[p] = g_src[e];
}

// ---------------- weight transpose -> fp16 plane (zeroes stats accumulators) --------------
__global__ void splitW_kernel(const float* __restrict__ W) {
    int idx = blockIdx.x * blockDim.x + threadIdx.x;
    if (idx < 256) { g_colsum[idx] = 0.f; g_colsumsq[idx] = 0.f; }
    if (idx >= 256 * 256) return;
    int k = idx >> 8;
    int n = idx & 255;
    ((__half*)g_Whi4)[n * 256 + k] = __float2half_rn(W[idx]);
}

// W2 [256,40] -> plane rows 0..127 (rows 40..127 zero), [n][k] fp16
__global__ void splitW2_kernel(const float* __restrict__ W2) {
    int idx = blockIdx.x * blockDim.x + threadIdx.x;   // 128*256
    if (idx >= 128 * 256) return;
    int n = idx >> 8;
    int k = idx & 255;
    float v = (n < LL) ? W2[k * LL + n] : 0.f;
    ((__half*)g_Whi4)[n * 256 + k] = __float2half_rn(v);
}

// ---------------- mma.sync fp16 GEMM with cp.async double-buffered pipeline --------------
#define CB_A   0
#define CB_B   16384
#define CB_SZ  32768
#define MMA_SMEM (2 * CB_SZ)

__global__ void __launch_bounds__(256, 2) mma_gemm_kernel(
    const __half* __restrict__ A16, const __half* __restrict__ B_g,
    __half* __restrict__ C16, int M, int ostride, int ncols,
    int doAl, float* __restrict__ alsP, float* __restrict__ aldP,
    const float* __restrict__ a_src, const float* __restrict__ a_dst) {
    extern __shared__ char smem[];
    uint32_t sb = smem_u32(smem);
    int tid = threadIdx.x;
    int wid = tid >> 5, lane = tid & 31;
    int bm = blockIdx.y * 128;
    int bn = blockIdx.x * 128;
    int wm = (wid >> 1) * 32;
    int wn = (wid & 1) * 64;

    float acc[2][8][4];
#pragma unroll
    for (int mt = 0; mt < 2; mt++)
#pragma unroll
        for (int nt = 0; nt < 8; nt++)
#pragma unroll
            for (int r = 0; r < 4; r++) acc[mt][nt][r] = 0.f;

    uint32_t b_row[4], b_cb;
#pragma unroll
    for (int ntp = 0; ntp < 4; ntp++)
        b_row[ntp] = (uint32_t)(wn + ntp * 16 + (lane & 7) + ((lane >> 4) << 3));
    b_cb = (uint32_t)(((lane >> 3) & 1) * 16);

#define STAGE(ch, buf)                                                                  \
    do {                                                                                \
        int _k0 = (ch) * 64;                                                            \
        uint32_t _base = sb + (buf) * CB_SZ;                                            \
        _Pragma("unroll")                                                               \
        for (int _i = 0; _i < 4; _i++) {                                                \
            int _lin = tid + _i * 256;                                                  \
            int _row = _lin >> 3, _sg = _lin & 7;                                       \
            uint32_t _so = swz128((uint32_t)(_row * 128 + _sg * 16));                   \
            int _gr = bm + _row;                                                        \
            const __half* _sa = A16 + (size_t)(_gr < M ? _gr : M - 1) * 256 + _k0 + _sg * 8; \
            CP_ASYNC16(_base + CB_A + _so, _sa, (_gr < M) ? 16 : 0);                    \
            const __half* _sb2 = B_g + (size_t)(bn + _row) * 256 + _k0 + _sg * 8;       \
            CP_ASYNC16(_base + CB_B + _so, _sb2, 16);                                   \
        }                                                                               \
        CP_COMMIT();                                                                    \
    } while (0)

    STAGE(0, 0);
    for (int ch = 0; ch < 4; ch++) {
        int buf = ch & 1;
        if (ch < 3) { STAGE(ch + 1, buf ^ 1); CP_WAIT1(); }
        else        { CP_WAIT0(); }
        __syncthreads();
        uint32_t base = sb + buf * CB_SZ;
#pragma unroll
        for (int ks = 0; ks < 4; ks++) {
            uint32_t kb = (uint32_t)(ks * 32);
            uint32_t a[2][4];
#pragma unroll
            for (int mt = 0; mt < 2; mt++) {
                uint32_t row = (uint32_t)(wm + mt * 16 + (lane & 15));
                uint32_t cb = (uint32_t)((lane >> 4) * 16) + kb;
                uint32_t ad = base + CB_A + swz128(row * 128 + cb);
                LDSM_X4(a[mt][0], a[mt][1], a[mt][2], a[mt][3], ad);
            }
            uint32_t bh[8][2];
#pragma unroll
            for (int ntp = 0; ntp < 4; ntp++) {
                uint32_t bo = swz128(b_row[ntp] * 128 + b_cb + kb);
                LDSM_X4(bh[2 * ntp][0], bh[2 * ntp][1], bh[2 * ntp + 1][0],
                        bh[2 * ntp + 1][1], base + CB_B + bo);
            }
#pragma unroll
            for (int mt = 0; mt < 2; mt++)
#pragma unroll
                for (int nt = 0; nt < 8; nt++)
                    MMAF16(acc[mt][nt], a[mt], bh[nt]);
        }
        __syncthreads();
    }
#undef STAGE

    // ---- epilogue ----
#pragma unroll
    for (int mt = 0; mt < 2; mt++) {
        int r0 = bm + wm + mt * 16 + (lane >> 2);
        int r1 = r0 + 8;
        float ds0 = 0.f, dd0 = 0.f, ds1 = 0.f, dd1 = 0.f;
#pragma unroll
        for (int nt = 0; nt < 8; nt++) {
            int col = bn + wn + nt * 8 + (lane & 3) * 2;
            if (col < ncols) {
                if (r0 < M) *(__half2*)(C16 + (size_t)r0 * ostride + col) =
                    __floats2half2_rn(acc[mt][nt][0], acc[mt][nt][1]);
                if (r1 < M) *(__half2*)(C16 + (size_t)r1 * ostride + col) =
                    __floats2half2_rn(acc[mt][nt][2], acc[mt][nt][3]);
            }
            if (doAl) {
                float as0 = a_src[col], as1 = a_src[col + 1];
                float ad0 = a_dst[col], ad1 = a_dst[col + 1];
                ds0 += acc[mt][nt][0] * as0 + acc[mt][nt][1] * as1;
                dd0 += acc[mt][nt][0] * ad0 + acc[mt][nt][1] * ad1;
                ds1 += acc[mt][nt][2] * as0 + acc[mt][nt][3] * as1;
                dd1 += acc[mt][nt][2] * ad0 + acc[mt][nt][3] * ad1;
            }
        }
        if (doAl) {
#pragma unroll
            for (int o = 1; o < 4; o <<= 1) {
                ds0 += __shfl_xor_sync(0xffffffffu, ds0, o);
                dd0 += __shfl_xor_sync(0xffffffffu, dd0, o);
                ds1 += __shfl_xor_sync(0xffffffffu, ds1, o);
                dd1 += __shfl_xor_sync(0xffffffffu, dd1, o);
            }
            if ((lane & 3) == 0) {
                if (r0 < M) { atomicAdd(&alsP[r0], ds0); atomicAdd(&aldP[r0], dd0); }
                if (r1 < M) { atomicAdd(&alsP[r1], ds1); atomicAdd(&aldP[r1], dd1); }
            }
        }
    }
}

// ---------------- GEMM-1 variant: A staged from fp32 x with inline standardize -----------
__global__ void __launch_bounds__(256, 2) mma_gemm_std_kernel(
    const float* __restrict__ A32, const __half* __restrict__ B_g,
    __half* __restrict__ C16, int M) {
    extern __shared__ char smem[];
    uint32_t sb = smem_u32(smem);
    int tid = threadIdx.x;
    int wid = tid >> 5, lane = tid & 31;
    int bm = blockIdx.y * 128;
    int bn = blockIdx.x * 128;
    int wm = (wid >> 1) * 32;
    int wn = (wid & 1) * 64;

    float acc[2][8][4];
#pragma unroll
    for (int mt = 0; mt < 2; mt++)
#pragma unroll
        for (int nt = 0; nt < 8; nt++)
#pragma unroll
            for (int r = 0; r < 4; r++) acc[mt][nt][r] = 0.f;

    uint32_t b_row[4], b_cb;
#pragma unroll
    for (int ntp = 0; ntp < 4; ntp++)
        b_row[ntp] = (uint32_t)(wn + ntp * 16 + (lane & 7) + ((lane >> 4) << 3));
    b_cb = (uint32_t)(((lane >> 3) & 1) * 16);

#define STAGE_STD(ch, buf)                                                              \
    do {                                                                                \
        int _k0 = (ch) * 64;                                                            \
        uint32_t _base = sb + (buf) * CB_SZ;                                            \
        _Pragma("unroll")                                                               \
        for (int _i = 0; _i < 4; _i++) {                                                \
            int _lin = tid + _i * 256;                                                  \
            int _row = _lin >> 3, _sg = _lin & 7;                                       \
            uint32_t _so = swz128((uint32_t)(_row * 128 + _sg * 16));                   \
            const __half* _sb2 = B_g + (size_t)(bn + _row) * 256 + _k0 + _sg * 8;       \
            CP_ASYNC16(_base + CB_B + _so, _sb2, 16);                                   \
        }                                                                               \
        CP_COMMIT();                                                                    \
        _Pragma("unroll")                                                               \
        for (int _i = 0; _i < 8; _i++) {                                                \
            int _lin = tid + _i * 256;                                                  \
            int _row = _lin >> 4;                                                       \
            int _c4 = (_lin & 15) * 4;                                                  \
            int _gr = bm + _row;                                                        \
            float4 _v = make_float4(0.f, 0.f, 0.f, 0.f);                                \
            if (_gr < M) _v = *(const float4*)(A32 + (size_t)_gr * 256 + _k0 + _c4);    \
            int _cc = _k0 + _c4;                                                        \
            _v.x = (_v.x - g_mean[_cc + 0]) * g_istd[_cc + 0];                          \
            _v.y = (_v.y - g_mean[_cc + 1]) * g_istd[_cc + 1];                          \
            _v.z = (_v.z - g_mean[_cc + 2]) * g_istd[_cc + 2];                          \
            _v.w = (_v.w - g_mean[_cc + 3]) * g_istd[_cc + 3];                          \
            __half2 _h01 = __floats2half2_rn(_v.x, _v.y);                               \
            __half2 _h23 = __floats2half2_rn(_v.z, _v.w);                               \
            uint32_t _so = swz128((uint32_t)(_row * 128 + _c4 * 2));                    \
            *(uint2*)(smem + (buf) * CB_SZ + CB_A + _so) =                              \
                make_uint2(*(uint32_t*)&_h01, *(uint32_t*)&_h23);                       \
        }                                                                               \
    } while (0)

    STAGE_STD(0, 0);
    for (int ch = 0; ch < 4; ch++) {
        int buf = ch & 1;
        if (ch < 3) { STAGE_STD(ch + 1, buf ^ 1); CP_WAIT1(); }
        else        { CP_WAIT0(); }
        __syncthreads();
        uint32_t base = sb + buf * CB_SZ;
#pragma unroll
        for (int ks = 0; ks < 4; ks++) {
            uint32_t kb = (uint32_t)(ks * 32);
            uint32_t a[2][4];
#pragma unroll
            for (int mt = 0; mt < 2; mt++) {
                uint32_t row = (uint32_t)(wm + mt * 16 + (lane & 15));
                uint32_t cb = (uint32_t)((lane >> 4) * 16) + kb;
                uint32_t ad = base + CB_A + swz128(row * 128 + cb);
                LDSM_X4(a[mt][0], a[mt][1], a[mt][2], a[mt][3], ad);
            }
            uint32_t bh[8][2];
#pragma unroll
            for (int ntp = 0; ntp < 4; ntp++) {
                uint32_t bo = swz128(b_row[ntp] * 128 + b_cb + kb);
                LDSM_X4(bh[2 * ntp][0], bh[2 * ntp][1], bh[2 * ntp + 1][0],
                        bh[2 * ntp + 1][1], base + CB_B + bo);
            }
#pragma unroll
            for (int mt = 0; mt < 2; mt++)
#pragma unroll
                for (int nt = 0; nt < 8; nt++)
                    MMAF16(acc[mt][nt], a[mt], bh[nt]);
        }
        __syncthreads();
    }
#undef STAGE_STD

    // ---- epilogue: fp16 store only (no attention logits for GEMM-1) ----
#pragma unroll
    for (int mt = 0; mt < 2; mt++) {
        int r0 = bm + wm + mt * 16 + (lane >> 2);
        int r1 = r0 + 8;
#pragma unroll
        for (int nt = 0; nt < 8; nt++) {
            int col = bn + wn + nt * 8 + (lane & 3) * 2;
            if (r0 < M) *(__half2*)(C16 + (size_t)r0 * 256 + col) =
                __floats2half2_rn(acc[mt][nt][0], acc[mt][nt][1]);
            if (r1 < M) *(__half2*)(C16 + (size_t)r1 * 256 + col) =
                __floats2half2_rn(acc[mt][nt][2], acc[mt][nt][3]);
        }
    }
}

// ---- fp16 row gather/store helpers ----
__device__ __forceinline__ void h16_accum(const uint2* __restrict__ hp, int idx, float w,
                                          float4& a0, float4& a1) {
    uint2 u0 = hp[idx];
    uint2 u1 = hp[idx + 32];
    float2 f0 = __half22float2(*(__half2*)&u0.x);
    float2 f1 = __half22float2(*(__half2*)&u0.y);
    float2 f2 = __half22float2(*(__half2*)&u1.x);
    float2 f3 = __half22float2(*(__half2*)&u1.y);
    a0.x += w * f0.x; a0.y += w * f0.y; a0.z += w * f1.x; a0.w += w * f1.y;
    a1.x += w * f2.x; a1.y += w * f2.y; a1.z += w * f3.x; a1.w += w * f3.y;
}

__device__ __forceinline__ void h16_store(uint2* __restrict__ o, int node, int lane,
                                          const float4& a0, const float4& a1) {
    __half2 h01 = __floats2half2_rn(a0.x, a0.y);
    __half2 h23 = __floats2half2_rn(a0.z, a0.w);
    uint2 u0 = make_uint2(*(uint32_t*)&h01, *(uint32_t*)&h23);
    __half2 h45 = __floats2half2_rn(a1.x, a1.y);
    __half2 h67 = __floats2half2_rn(a1.z, a1.w);
    uint2 u1 = make_uint2(*(uint32_t*)&h45, *(uint32_t*)&h67);
    o[(size_t)node * 64 + lane] = u0;
    o[(size_t)node * 64 + lane + 32] = u1;
}

// ---------------- GCN aggregate (warp per dst node, fp16 in/out, unroll-4) ---------------
__global__ void gcn_agg_kernel(const uint2* __restrict__ h, const float* __restrict__ bias,
                               uint2* __restrict__ out) {
    int t = blockIdx.x * blockDim.x + threadIdx.x;
    int node = t >> 5;
    int lane = t & 31;
    if (node >= NN) return;
    int beg = g_rowptr[node], end = g_rowptr[node + 1];
    float di = g_dinv[node];
    float4 a0 = make_float4(0.f, 0.f, 0.f, 0.f);
    float4 a1 = make_float4(0.f, 0.f, 0.f, 0.f);
    h16_accum(h, node * 64 + lane, di * di, a0, a1);
    int e = beg;
    for (; e + 4 <= end; e += 4) {
        int s0 = g_col[e], s1 = g_col[e + 1], s2 = g_col[e + 2], s3 = g_col[e + 3];
        float w0 = g_dinv[s0] * di, w1 = g_dinv[s1] * di;
        float w2 = g_dinv[s2] * di, w3 = g_dinv[s3] * di;
        h16_accum(h, s0 * 64 + lane, w0, a0, a1);
        h16_accum(h, s1 * 64 + lane, w1, a0, a1);
        h16_accum(h, s2 * 64 + lane, w2, a0, a1);
        h16_accum(h, s3 * 64 + lane, w3, a0, a1);
    }
    for (; e < end; e++) {
        int s = g_col[e];
        h16_accum(h, s * 64 + lane, g_dinv[s] * di, a0, a1);
    }
    float4 b0 = ((const float4*)bias)[lane];
    float4 b1 = ((const float4*)bias)[lane + 32];
    a0.x = fmaxf(a0.x + b0.x, 0.f); a0.y = fmaxf(a0.y + b0.y, 0.f);
    a0.z = fmaxf(a0.z + b0.z, 0.f); a0.w = fmaxf(a0.w + b0.w, 0.f);
    a1.x = fmaxf(a1.x + b1.x, 0.f); a1.y = fmaxf(a1.y + b1.y, 0.f);
    a1.z = fmaxf(a1.z + b1.z, 0.f); a1.w = fmaxf(a1.w + b1.w, 0.f);
    h16_store(out, node, lane, a0, a1);
}

// ---------------- GAT aggregate with segment softmax (fp16 in/out, unroll-4) -------------
__global__ void gat_agg_kernel(const uint2* __restrict__ h, const float* __restrict__ bias,
                               uint2* __restrict__ out,
                               const float* __restrict__ alsP, const float* __restrict__ aldP) {
    int t = blockIdx.x * blockDim.x + threadIdx.x;
    int node = t >> 5;
    int lane = t & 31;
    if (node >= NN) return;
    int beg = g_rowptr[node], end = g_rowptr[node + 1];
    float aldi = aldP[node];
    float e_self = lrelu(alsP[node] + aldi);
    float m = e_self;
    for (int e = beg + lane; e < end; e += 32)
        m = fmaxf(m, lrelu(alsP[g_col[e]] + aldi));
    for (int o = 16; o; o >>= 1) m = fmaxf(m, __shfl_xor_sync(0xffffffffu, m, o));
    float z = __expf(e_self - m);
    float4 a0 = make_float4(0.f, 0.f, 0.f, 0.f);
    float4 a1 = make_float4(0.f, 0.f, 0.f, 0.f);
    h16_accum(h, node * 64 + lane, z, a0, a1);
    int e = beg;
    for (; e + 4 <= end; e += 4) {
        int s0 = g_col[e], s1 = g_col[e + 1], s2 = g_col[e + 2], s3 = g_col[e + 3];
        float w0 = __expf(lrelu(alsP[s0] + aldi) - m);
        float w1 = __expf(lrelu(alsP[s1] + aldi) - m);
        float w2 = __expf(lrelu(alsP[s2] + aldi) - m);
        float w3 = __expf(lrelu(alsP[s3] + aldi) - m);
        z += w0 + w1 + w2 + w3;
        h16_accum(h, s0 * 64 + lane, w0, a0, a1);
        h16_accum(h, s1 * 64 + lane, w1, a0, a1);
        h16_accum(h, s2 * 64 + lane, w2, a0, a1);
        h16_accum(h, s3 * 64 + lane, w3, a0, a1);
    }
    for (; e < end; e++) {
        int s = g_col[e];
        float w = __expf(lrelu(alsP[s] + aldi) - m);
        z += w;
        h16_accum(h, s * 64 + lane, w, a0, a1);
    }
    float inv = 1.0f / z;
    float4 b0 = ((const float4*)bias)[lane];
    float4 b1 = ((const float4*)bias)[lane + 32];
    a0.x = fmaxf(a0.x * inv + b0.x, 0.f); a0.y = fmaxf(a0.y * inv + b0.y, 0.f);
    a0.z = fmaxf(a0.z * inv + b0.z, 0.f); a0.w = fmaxf(a0.w * inv + b0.w, 0.f);
    a1.x = fmaxf(a1.x * inv + b1.x, 0.f); a1.y = fmaxf(a1.y * inv + b1.y, 0.f);
    a1.z = fmaxf(a1.z * inv + b1.z, 0.f); a1.w = fmaxf(a1.w * inv + b1.w, 0.f);
    h16_store(out, node, lane, a0, a1);
}

// ---------------- final GCN (L=40) + log_softmax: 20 active lanes x half2 ----------------
__global__ void gcn2_kernel(const __half* __restrict__ h2, const float* __restrict__ b2,
                            float* __restrict__ out) {
    int t = blockIdx.x * blockDim.x + threadIdx.x;
    int node = t >> 5;
    int lane = t & 31;
    if (node >= NN) return;
    int beg = g_rowptr[node], end = g_rowptr[node + 1];
    float di = g_dinv[node];
    bool act = lane < 20;
    const __half2* hp = (const __half2*)h2;   // row stride 20 half2
    float2 acc = make_float2(0.f, 0.f);
    float w = di * di;
    if (act) {
        float2 f = __half22float2(hp[node * 20 + lane]);
        acc.x = w * f.x; acc.y = w * f.y;
    }
    int e = beg;
    for (; e + 4 <= end; e += 4) {
        int s0 = g_col[e], s1 = g_col[e + 1], s2 = g_col[e + 2], s3 = g_col[e + 3];
        float w0 = g_dinv[s0] * di, w1 = g_dinv[s1] * di;
        float w2 = g_dinv[s2] * di, w3 = g_dinv[s3] * di;
        if (act) {
            float2 f0 = __half22float2(hp[s0 * 20 + lane]);
            float2 f1 = __half22float2(hp[s1 * 20 + lane]);
            float2 f2 = __half22float2(hp[s2 * 20 + lane]);
            float2 f3 = __half22float2(hp[s3 * 20 + lane]);
            acc.x += w0 * f0.x + w1 * f1.x + w2 * f2.x + w3 * f3.x;
            acc.y += w0 * f0.y + w1 * f1.y + w2 * f2.y + w3 * f3.y;
        }
    }
    for (; e < end; e++) {
        int s = g_col[e];
        float we = g_dinv[s] * di;
        if (act) {
            float2 f = __half22float2(hp[s * 20 + lane]);
            acc.x += we * f.x; acc.y += we * f.y;
        }
    }
    float v0 = act ? acc.x + b2[lane * 2] : -INFINITY;
    float v1 = act ? acc.y + b2[lane * 2 + 1] : -INFINITY;
    float m = fmaxf(v0, v1);
    for (int o = 16; o; o >>= 1) m = fmaxf(m, __shfl_xor_sync(0xffffffffu, m, o));
    float z = act ? (expf(v0 - m) + expf(v1 - m)) : 0.f;
    for (int o = 16; o; o >>= 1) z += __shfl_xor_sync(0xffffffffu, z, o);
    float ls = logf(z);
    if (act)
        *(float2*)(out + (size_t)node * LL + lane * 2) = make_float2(v0 - m - ls, v1 - m - ls);
}

// ---------------- launch ----------------
extern "C" void kernel_launch(void* const* d_in, const int* in_sizes, int n_in,
                              void* d_out, int out_size) {
    const float* x   = (const float*)d_in[0];
    const void*  ei  = d_in[1];
    const float* W1  = (const float*)d_in[2];
    const float* b1  = (const float*)d_in[3];
    const float* Wg  = (const float*)d_in[4];
    const float* a_s = (const float*)d_in[5];
    const float* a_d = (const float*)d_in[6];
    const float* bg  = (const float*)d_in[7];
    const float* W2  = (const float*)d_in[8];
    const float* b2  = (const float*)d_in[9];
    float* out = (float*)d_out;

    uint2 *pH16, *pX16;
    __half* pH2;
    __half* pWhi;
    float *pAls, *pAld, *pAls2, *pAld2;
    cudaGetSymbolAddress((void**)&pH16, g_h16);
    cudaGetSymbolAddress((void**)&pX16, g_x16);
    cudaGetSymbolAddress((void**)&pH2, g_h2);
    cudaGetSymbolAddress((void**)&pWhi, g_Whi4);
    cudaGetSymbolAddress((void**)&pAls, g_als);
    cudaGetSymbolAddress((void**)&pAld, g_ald);
    cudaGetSymbolAddress((void**)&pAls2, g_als2);
    cudaGetSymbolAddress((void**)&pAld2, g_ald2);

    cudaFuncSetAttribute(mma_gemm_kernel, cudaFuncAttributeMaxDynamicSharedMemorySize, MMA_SMEM);
    cudaFuncSetAttribute(mma_gemm_std_kernel, cudaFuncAttributeMaxDynamicSharedMemorySize, MMA_SMEM);

    const int tpb = 256;
    dim3 gMMA(2, (NN + 127) / 128);
    dim3 gMMA2(1, (NN + 127) / 128);
    int warpGrid = (NN * 32 + tpb - 1) / tpb;
    int zg = (NN + tpb - 1) / tpb;

    // side stream + fork/join events (capture-compatible fork/join pattern)
    cudaStream_t s2;
    cudaStreamCreateWithFlags(&s2, cudaStreamNonBlocking);
    cudaEvent_t evFork, evCsr, evG1, evW, evG3, evW2;
    cudaEventCreateWithFlags(&evFork, cudaEventDisableTiming);
    cudaEventCreateWithFlags(&evCsr, cudaEventDisableTiming);
    cudaEventCreateWithFlags(&evG1, cudaEventDisableTiming);
    cudaEventCreateWithFlags(&evW, cudaEventDisableTiming);
    cudaEventCreateWithFlags(&evG3, cudaEventDisableTiming);
    cudaEventCreateWithFlags(&evW2, cudaEventDisableTiming);

    // ---- fork: CSR build on s2, concurrent with stats/GEMM-1 on main ----
    cudaEventRecord(evFork, 0);
    cudaStreamWaitEvent(s2, evFork, 0);
    zero_kernel<<<zg, tpb, 0, s2>>>();
    detect_kernel<<<1, 32, 0, s2>>>((const unsigned int*)ei);
    convert_kernel<<<(EE + tpb - 1) / tpb, tpb, 0, s2>>>(ei);
    dinv_kernel<<<zg, tpb, 0, s2>>>();
    scan_kernel<<<1, 1024, 0, s2>>>();
    fill_kernel<<<(EE + tpb - 1) / tpb, tpb, 0, s2>>>();
    cudaEventRecord(evCsr, s2);

    // ---- main: GEMM-1 (dedicated std kernel, reads x fp32 directly) ----
    splitW_kernel<<<(256 * 256) / tpb, tpb>>>(W1);   // also zeroes colsum/colsumsq
    stats_kernel<<<296, 256>>>(x);
    finalize_kernel<<<1, 256>>>();
    mma_gemm_std_kernel<<<gMMA, 256, MMA_SMEM>>>(x, pWhi, (__half*)pH16, NN);
    cudaEventRecord(evG1, 0);

    // fork: splitW(Wg) + zero both al-buffer pairs on s2, overlapping gcn_agg on main
    cudaStreamWaitEvent(s2, evG1, 0);
    splitW_kernel<<<(256 * 256) / tpb, tpb, 0, s2>>>(Wg);
    zero_al_kernel<<<zg, tpb, 0, s2>>>();
    cudaEventRecord(evW, s2);

    // main: join CSR, then GCN aggregate (+ReLU) -> x16
    cudaStreamWaitEvent(0, evCsr, 0);
    gcn_agg_kernel<<<warpGrid, tpb>>>(pH16, b1, pX16);

    // GAT layer 1 (+ReLU): logits -> als/ald
    cudaStreamWaitEvent(0, evW, 0);
    mma_gemm_kernel<<<gMMA, 256, MMA_SMEM>>>((const __half*)pX16, pWhi,
                                             (__half*)pH16, NN, 256, 256, 1,
                                             pAls, pAld, a_s, a_d);
    gat_agg_kernel<<<warpGrid, tpb>>>(pH16, bg, pX16, pAls, pAld);

    // GAT layer 2 (+ReLU): logits -> als2/ald2 (pre-zeroed on s2)
    mma_gemm_kernel<<<gMMA, 256, MMA_SMEM>>>((const __half*)pX16, pWhi,
                                             (__half*)pH16, NN, 256, 256, 1,
                                             pAls2, pAld2, a_s, a_d);
    cudaEventRecord(evG3, 0);

    // fork: splitW2(W2) on s2 overlapping gat_agg2 on main
    cudaStreamWaitEvent(s2, evG3, 0);
    splitW2_kernel<<<(128 * 256) / tpb, tpb, 0, s2>>>(W2);
    cudaEventRecord(evW2, s2);

    gat_agg_kernel<<<warpGrid, tpb>>>(pH16, bg, pX16, pAls2, pAld2);

    // GCN layer 2 (tensor-core, N padded to 128, fp16 out, stride LL halves) + log_softmax
    cudaStreamWaitEvent(0, evW2, 0);
    mma_gemm_kernel<<<gMMA2, 256, MMA_SMEM>>>((const __half*)pX16, pWhi,
                                              pH2, NN, LL, LL, 0,
                                              pAls, pAld, a_s, a_d);
    gcn2_kernel<<<warpGrid, tpb>>>(pH2, b2, out);

    cudaEventDestroy(evFork);
    cudaEventDestroy(evCsr);
    cudaEventDestroy(evG1);
    cudaEventDestroy(evW);
    cudaEventDestroy(evG3);
    cudaEventDestroy(evW2);
    cudaStreamDestroy(s2);
}